// round 1
// baseline (speedup 1.0000x reference)
#include <cuda_runtime.h>
#include <cstdint>
#include <cstddef>

#define NN 100000
#define NE 1600000

// ---------------- scratch (static device globals; no allocs allowed) ----------------
__device__ __align__(16) float g_deg[NN];
__device__ __align__(16) float g_dinv[NN];
__device__ int g_src[NE];
__device__ int g_dst[NE];
__device__ __align__(16) float g_agg1[(size_t)NN * 40];
__device__ __align__(16) float g_h1[(size_t)NN * 64];
__device__ __align__(16) float g_agg2[(size_t)NN * 64];
__device__ __align__(16) float g_h2[(size_t)NN * 128];
__device__ __align__(16) float g_z[(size_t)NN * 4];
__device__ __align__(16) float g_agg3[(size_t)NN * 4];

// vector reduction (sm_90+): one L2 op for 4 floats
__device__ __forceinline__ void red_add_f4(float* addr, float4 v) {
    asm volatile("red.global.add.v4.f32 [%0], {%1,%2,%3,%4};"
                 :: "l"(addr), "f"(v.x), "f"(v.y), "f"(v.z), "f"(v.w)
                 : "memory");
}

// ---------------- zero all accumulators (deg, agg1, agg2, agg3) ----------------
// float4 units: deg 25000, agg1 1,000,000, agg2 1,600,000, agg3 100,000 => 2,725,000
__global__ void k_zero() {
    int i = blockIdx.x * blockDim.x + threadIdx.x;
    float4 z = make_float4(0.f, 0.f, 0.f, 0.f);
    if (i < 25000)        reinterpret_cast<float4*>(g_deg)[i] = z;
    else if (i < 1025000) reinterpret_cast<float4*>(g_agg1)[i - 25000] = z;
    else if (i < 2625000) reinterpret_cast<float4*>(g_agg2)[i - 1025000] = z;
    else if (i < 2725000) reinterpret_cast<float4*>(g_agg3)[i - 2625000] = z;
}

// ---------------- edge conversion (+degree count), int64/int32 auto-detect ----------------
__global__ void k_edges(const int* __restrict__ ei32) {
    // If the tensor is int64, every odd 32-bit word of the first entries is 0
    // (values are in [0, 100000)). If int32, they are random node ids.
    bool is64 = true;
#pragma unroll
    for (int q = 1; q < 16; q += 2) is64 = is64 && (ei32[q] == 0);
    int e = blockIdx.x * blockDim.x + threadIdx.x;
    if (e >= NE) return;
    int s, d;
    if (is64) { s = ei32[2 * e];  d = ei32[2 * (NE + e)]; }
    else      { s = ei32[e];      d = ei32[NE + e]; }
    g_src[e] = s;
    g_dst[e] = d;
    atomicAdd(&g_deg[d], 1.0f);
}

__global__ void k_dinv() {
    int i = blockIdx.x * blockDim.x + threadIdx.x;
    if (i < NN) {
        float d = g_deg[i];
        g_dinv[i] = (d > 0.f) ? (1.f / d) : 0.f;
    }
}

// ---------------- scatter: agg[dst] += feat[src], F4 float4-chunks per edge ----------------
template <int F4>
__global__ void k_scatter(const float* __restrict__ feat, float* __restrict__ agg) {
    int t = blockIdx.x * blockDim.x + threadIdx.x;
    if (t >= NE * F4) return;
    int e = t / F4;
    int c = t - e * F4;
    int s = g_src[e];
    int d = g_dst[e];
    float4 v = reinterpret_cast<const float4*>(feat)[(size_t)s * F4 + c];
    red_add_f4(agg + ((size_t)d * F4 + c) * 4, v);
}

// ---------------- fused SAGE layer: out = act( (agg*dinv)@Wl^T + b + in@Wr^T ) ----------------
// 64 threads/block = 64 output columns (blockIdx.y selects column block).
// R=4 rows per iteration so each smem weight read feeds 4 FMAs -> FMA-bound, not LDS-bound.
template <int K, bool RELU>
__global__ void k_layer(const float* __restrict__ in, const float* __restrict__ agg,
                        const float* __restrict__ Wl, const float* __restrict__ bias,
                        const float* __restrict__ Wr, float* __restrict__ out, int Mtot) {
    constexpr int MB = 64;
    constexpr int K4 = K / 4;
    constexpr int K4P = K4 + 1;  // odd float4 stride -> conflict-free LDS.128
    __shared__ float4 sWl[MB * K4P];
    __shared__ float4 sWr[MB * K4P];
    __shared__ float sb[MB];
    __shared__ float4 sIn[4 * K4];
    __shared__ float4 sAg[4 * K4];

    int tid = threadIdx.x;
    int coff = blockIdx.y * MB;

    for (int idx = tid; idx < MB * K; idx += MB) {
        int row = idx / K, col = idx - row * K;
        reinterpret_cast<float*>(&sWl[row * K4P])[col] = Wl[(size_t)(coff + row) * K + col];
        reinterpret_cast<float*>(&sWr[row * K4P])[col] = Wr[(size_t)(coff + row) * K + col];
    }
    sb[tid] = bias[coff + tid];

    for (int r0 = blockIdx.x * 4; r0 < NN; r0 += gridDim.x * 4) {
        __syncthreads();
        if (tid < K) {  // K float4 chunks cover 4 rows (rows are contiguous)
            sIn[tid] = reinterpret_cast<const float4*>(in + (size_t)r0 * K)[tid];
            sAg[tid] = reinterpret_cast<const float4*>(agg + (size_t)r0 * K)[tid];
        }
        __syncthreads();

        float accl[4] = {0.f, 0.f, 0.f, 0.f};
        float accr[4] = {0.f, 0.f, 0.f, 0.f};
        const float4* wl = &sWl[tid * K4P];
        const float4* wr = &sWr[tid * K4P];
#pragma unroll
        for (int k = 0; k < K4; k++) {
            float4 l = wl[k];
            float4 rr = wr[k];
#pragma unroll
            for (int q = 0; q < 4; q++) {
                float4 a = sAg[q * K4 + k];
                float4 xv = sIn[q * K4 + k];
                accl[q] += a.x * l.x + a.y * l.y + a.z * l.z + a.w * l.w;
                accr[q] += xv.x * rr.x + xv.y * rr.y + xv.z * rr.z + xv.w * rr.w;
            }
        }
        float bv = sb[tid];
#pragma unroll
        for (int q = 0; q < 4; q++) {
            float dinv = g_dinv[r0 + q];
            float acc = bv + dinv * accl[q] + accr[q];
            if (RELU) acc = fmaxf(acc, 0.f);
            out[(size_t)(r0 + q) * Mtot + coff + tid] = acc;
        }
    }
}

// ---------------- layer 3 part A: z = h2@W4l^T (padded to 4), out = h2@W4r^T + b4 ----------------
__global__ void k_l3a(const float* __restrict__ W4l, const float* __restrict__ b4,
                      const float* __restrict__ W4r, float* __restrict__ out) {
    __shared__ float swl[384], swr[384], sb[3];
    int tid = threadIdx.x;
    for (int i = tid; i < 384; i += blockDim.x) { swl[i] = W4l[i]; swr[i] = W4r[i]; }
    if (tid < 3) sb[tid] = b4[tid];
    __syncthreads();
    int r = blockIdx.x * blockDim.x + tid;
    if (r >= NN) return;
    const float4* h = reinterpret_cast<const float4*>(g_h2 + (size_t)r * 128);
    float l[3] = {0.f, 0.f, 0.f};
    float rr[3] = {0.f, 0.f, 0.f};
#pragma unroll
    for (int k4 = 0; k4 < 32; k4++) {
        float4 v = h[k4];
        float vv[4] = {v.x, v.y, v.z, v.w};
#pragma unroll
        for (int q = 0; q < 4; q++) {
            int k = k4 * 4 + q;
#pragma unroll
            for (int m = 0; m < 3; m++) {
                l[m] += vv[q] * swl[m * 128 + k];
                rr[m] += vv[q] * swr[m * 128 + k];
            }
        }
    }
    reinterpret_cast<float4*>(g_z)[r] = make_float4(l[0], l[1], l[2], 0.f);
#pragma unroll
    for (int m = 0; m < 3; m++) out[(size_t)r * 3 + m] = rr[m] + sb[m];
}

// ---------------- layer 3 part B: out += mean-aggregated z ----------------
__global__ void k_final(float* __restrict__ out) {
    int r = blockIdx.x * blockDim.x + threadIdx.x;
    if (r >= NN) return;
    float dinv = g_dinv[r];
#pragma unroll
    for (int m = 0; m < 3; m++) out[(size_t)r * 3 + m] += g_agg3[r * 4 + m] * dinv;
}

// ---------------- launch ----------------
extern "C" void kernel_launch(void* const* d_in, const int* in_sizes, int n_in,
                              void* d_out, int out_size) {
    (void)in_sizes; (void)n_in; (void)out_size;
    const float* x   = (const float*)d_in[0];
    const int*   ei  = (const int*)d_in[1];   // int32 view; k_edges auto-detects int64
    const float* W1l = (const float*)d_in[2];
    const float* b1  = (const float*)d_in[3];
    const float* W1r = (const float*)d_in[4];
    const float* W2l = (const float*)d_in[5];
    const float* b2  = (const float*)d_in[6];
    const float* W2r = (const float*)d_in[7];
    const float* W4l = (const float*)d_in[8];
    const float* b4  = (const float*)d_in[9];
    const float* W4r = (const float*)d_in[10];
    float* out = (float*)d_out;

    void *p_agg1, *p_agg2, *p_agg3, *p_h1, *p_h2, *p_z;
    cudaGetSymbolAddress(&p_agg1, g_agg1);
    cudaGetSymbolAddress(&p_agg2, g_agg2);
    cudaGetSymbolAddress(&p_agg3, g_agg3);
    cudaGetSymbolAddress(&p_h1, g_h1);
    cudaGetSymbolAddress(&p_h2, g_h2);
    cudaGetSymbolAddress(&p_z, g_z);

    k_zero<<<(2725000 + 255) / 256, 256>>>();
    k_edges<<<(NE + 255) / 256, 256>>>(ei);
    k_dinv<<<(NN + 255) / 256, 256>>>();

    // layer 1: aggregate x (40 f = 10 float4/edge), then fused linear -> h1 [N,64]
    k_scatter<10><<<(NE * 10 + 255) / 256, 256>>>(x, (float*)p_agg1);
    k_layer<40, true><<<dim3(1024, 1), 64>>>(x, (const float*)p_agg1, W1l, b1, W1r,
                                             (float*)p_h1, 64);

    // layer 2: aggregate h1 (64 f = 16 float4/edge), fused linear -> h2 [N,128]
    k_scatter<16><<<(NE * 16 + 255) / 256, 256>>>((const float*)p_h1, (float*)p_agg2);
    k_layer<64, true><<<dim3(1024, 2), 64>>>((const float*)p_h1, (const float*)p_agg2,
                                             W2l, b2, W2r, (float*)p_h2, 128);

    // layer 3: transform FIRST (3 outputs), aggregate only 4 floats/edge
    k_l3a<<<(NN + 127) / 128, 128>>>(W4l, b4, W4r, out);
    k_scatter<1><<<(NE + 255) / 256, 256>>>((const float*)p_z, (float*)p_agg3);
    k_final<<<(NN + 255) / 256, 256>>>(out);
}

// round 2
// speedup vs baseline: 1.0372x; 1.0372x over previous
#include <cuda_runtime.h>
#include <cstdint>
#include <cstddef>

#define NN 100000
#define NE 1600000
#define SCAN_B 512
#define SCAN_NB ((NN + SCAN_B - 1) / SCAN_B)   // 196

// ---------------- scratch (static device globals; no allocs allowed) ----------------
__device__ int   g_degi[NN];
__device__ float g_dinv[NN];
__device__ int   g_src[NE];
__device__ int   g_dst[NE];
__device__ int   g_csr[NE];
__device__ int   g_rowptr[NN + 1];
__device__ int   g_cursor[NN];
__device__ int   g_bsum[256];
__device__ int   g_boff[256];
__device__ __align__(16) float g_agg1[(size_t)NN * 40];
__device__ __align__(16) float g_h1[(size_t)NN * 64];
__device__ __align__(16) float g_agg2[(size_t)NN * 64];
__device__ __align__(16) float g_h2[(size_t)NN * 128];
__device__ __align__(16) float g_z[(size_t)NN * 4];

// ---------------- CSR build ----------------
__global__ void k_zero0() {
    int i = blockIdx.x * blockDim.x + threadIdx.x;
    if (i < NN) g_degi[i] = 0;
}

// edge conversion (+int histogram), int64/int32 auto-detect
__global__ void k_edges(const int* __restrict__ ei32) {
    bool is64 = true;
#pragma unroll
    for (int q = 1; q < 16; q += 2) is64 = is64 && (ei32[q] == 0);
    int e = blockIdx.x * blockDim.x + threadIdx.x;
    if (e >= NE) return;
    int s, d;
    if (is64) { s = ei32[2 * e];  d = ei32[2 * (NE + e)]; }
    else      { s = ei32[e];      d = ei32[NE + e]; }
    g_src[e] = s;
    g_dst[e] = d;
    atomicAdd(&g_degi[d], 1);
}

__global__ void k_scan1() {
    __shared__ int sh[SCAN_B];
    int i = blockIdx.x * SCAN_B + threadIdx.x;
    int v = (i < NN) ? g_degi[i] : 0;
    sh[threadIdx.x] = v;
    __syncthreads();
    for (int off = 1; off < SCAN_B; off <<= 1) {
        int t = (threadIdx.x >= off) ? sh[threadIdx.x - off] : 0;
        __syncthreads();
        sh[threadIdx.x] += t;
        __syncthreads();
    }
    if (i < NN) g_rowptr[i] = sh[threadIdx.x] - v;  // exclusive
    if (threadIdx.x == SCAN_B - 1) g_bsum[blockIdx.x] = sh[threadIdx.x];
}

__global__ void k_scan2() {
    __shared__ int sh[256];
    int t = threadIdx.x;
    int v = (t < SCAN_NB) ? g_bsum[t] : 0;
    sh[t] = v;
    __syncthreads();
    for (int off = 1; off < 256; off <<= 1) {
        int u = (t >= off) ? sh[t - off] : 0;
        __syncthreads();
        sh[t] += u;
        __syncthreads();
    }
    g_boff[t] = sh[t] - v;  // exclusive
}

__global__ void k_scan3() {
    int i = blockIdx.x * blockDim.x + threadIdx.x;
    if (i >= NN) return;
    int rp = g_rowptr[i] + g_boff[i / SCAN_B];
    g_rowptr[i] = rp;
    g_cursor[i] = rp;
    int d = g_degi[i];
    g_dinv[i] = (d > 0) ? (1.f / (float)d) : 0.f;
    if (i == 0) g_rowptr[NN] = NE;
}

__global__ void k_fill() {
    int e = blockIdx.x * blockDim.x + threadIdx.x;
    if (e >= NE) return;
    int pos = atomicAdd(&g_cursor[g_dst[e]], 1);
    g_csr[pos] = g_src[e];
}

// ---------------- CSR gather: agg[n] = dinv[n] * sum_{s in N(n)} feat[s] ----------------
template <int F4>
__global__ void k_gather(const float* __restrict__ feat, float* __restrict__ agg) {
    int t = blockIdx.x * blockDim.x + threadIdx.x;
    if (t >= NN * F4) return;
    int n = t / F4;
    int c = t - n * F4;
    int beg = g_rowptr[n], end = g_rowptr[n + 1];
    const float4* f = reinterpret_cast<const float4*>(feat);
    float4 acc = make_float4(0.f, 0.f, 0.f, 0.f);
    for (int i = beg; i < end; i++) {
        int s = g_csr[i];
        float4 v = f[(size_t)s * F4 + c];
        acc.x += v.x; acc.y += v.y; acc.z += v.z; acc.w += v.w;
    }
    float di = g_dinv[n];
    acc.x *= di; acc.y *= di; acc.z *= di; acc.w *= di;
    reinterpret_cast<float4*>(agg)[t] = acc;
}

// ---------------- fused SAGE layer: out = act( agg@Wl^T + b + in@Wr^T ) ----------------
// 256 threads = 16 colgrp x 16 rowgrp; thread computes 4 rows x 4 cols for BOTH matmuls.
// Each LDS.128 feeds 8 FMAs -> FMA-bound. Odd-f4 padding (K4+1) avoids bank conflicts.
template <int K, bool RELU>
__global__ void __launch_bounds__(256) k_layer(
        const float* __restrict__ in, const float* __restrict__ agg,
        const float* __restrict__ Wl, const float* __restrict__ bias,
        const float* __restrict__ Wr, float* __restrict__ out, int Mtot) {
    constexpr int K4 = K / 4;
    constexpr int K4P = K4 + 1;
    extern __shared__ float4 dyn[];
    float4* sWl = dyn;                 // 64*K4P
    float4* sWr = sWl + 64 * K4P;
    float4* sIn = sWr + 64 * K4P;      // 64 rows staged
    float4* sAg = sIn + 64 * K4P;
    float*  sb  = (float*)(sAg + 64 * K4P);  // 64 floats

    int tid = threadIdx.x;
    int coff = blockIdx.y * 64;

    for (int idx = tid; idx < 64 * K; idx += 256) {
        int r = idx / K, c = idx - r * K;
        reinterpret_cast<float*>(&sWl[r * K4P])[c] = Wl[(size_t)(coff + r) * K + c];
        reinterpret_cast<float*>(&sWr[r * K4P])[c] = Wr[(size_t)(coff + r) * K + c];
    }
    if (tid < 64) sb[tid] = bias[coff + tid];

    const float4* in4  = reinterpret_cast<const float4*>(in);
    const float4* agg4 = reinterpret_cast<const float4*>(agg);
    int rg = tid >> 4, cg = tid & 15;

    for (int r0 = blockIdx.x * 64; r0 < NN; r0 += gridDim.x * 64) {
        __syncthreads();
        for (int idx = tid; idx < 64 * K4; idx += 256) {
            int row = idx / K4, kk = idx - row * K4;
            int gr = r0 + row;
            float4 vi = make_float4(0.f, 0.f, 0.f, 0.f), va = vi;
            if (gr < NN) {
                vi = in4[(size_t)gr * K4 + kk];
                va = agg4[(size_t)gr * K4 + kk];
            }
            sIn[row * K4P + kk] = vi;
            sAg[row * K4P + kk] = va;
        }
        __syncthreads();

        float accl[4][4] = {}, accr[4][4] = {};
#pragma unroll
        for (int k = 0; k < K4; k++) {
            float4 fa[4], fi[4], wl[4], wr[4];
#pragma unroll
            for (int q = 0; q < 4; q++) {
                fa[q] = sAg[(rg * 4 + q) * K4P + k];
                fi[q] = sIn[(rg * 4 + q) * K4P + k];
            }
#pragma unroll
            for (int p = 0; p < 4; p++) {
                wl[p] = sWl[(cg * 4 + p) * K4P + k];
                wr[p] = sWr[(cg * 4 + p) * K4P + k];
            }
#pragma unroll
            for (int q = 0; q < 4; q++)
#pragma unroll
                for (int p = 0; p < 4; p++) {
                    accl[q][p] += fa[q].x * wl[p].x + fa[q].y * wl[p].y
                                + fa[q].z * wl[p].z + fa[q].w * wl[p].w;
                    accr[q][p] += fi[q].x * wr[p].x + fi[q].y * wr[p].y
                                + fi[q].z * wr[p].z + fi[q].w * wr[p].w;
                }
        }

        float b0 = sb[cg * 4 + 0], b1 = sb[cg * 4 + 1],
              b2 = sb[cg * 4 + 2], b3 = sb[cg * 4 + 3];
#pragma unroll
        for (int q = 0; q < 4; q++) {
            int row = r0 + rg * 4 + q;
            if (row < NN) {
                float4 o;
                o.x = accl[q][0] + accr[q][0] + b0;
                o.y = accl[q][1] + accr[q][1] + b1;
                o.z = accl[q][2] + accr[q][2] + b2;
                o.w = accl[q][3] + accr[q][3] + b3;
                if (RELU) {
                    o.x = fmaxf(o.x, 0.f); o.y = fmaxf(o.y, 0.f);
                    o.z = fmaxf(o.z, 0.f); o.w = fmaxf(o.w, 0.f);
                }
                *reinterpret_cast<float4*>(&out[(size_t)row * Mtot + coff + cg * 4]) = o;
            }
        }
    }
}

// ---------------- layer 3 part A: z = h2@W4l^T (padded to 4), out = h2@W4r^T + b4 ----------------
__global__ void k_l3a(const float* __restrict__ W4l, const float* __restrict__ b4,
                      const float* __restrict__ W4r, float* __restrict__ out) {
    __shared__ float swl[384], swr[384], sb[3];
    int tid = threadIdx.x;
    for (int i = tid; i < 384; i += blockDim.x) { swl[i] = W4l[i]; swr[i] = W4r[i]; }
    if (tid < 3) sb[tid] = b4[tid];
    __syncthreads();
    int r = blockIdx.x * blockDim.x + tid;
    if (r >= NN) return;
    const float4* h = reinterpret_cast<const float4*>(g_h2 + (size_t)r * 128);
    float l[3] = {0.f, 0.f, 0.f};
    float rr[3] = {0.f, 0.f, 0.f};
#pragma unroll
    for (int k4 = 0; k4 < 32; k4++) {
        float4 v = h[k4];
        float vv[4] = {v.x, v.y, v.z, v.w};
#pragma unroll
        for (int q = 0; q < 4; q++) {
            int k = k4 * 4 + q;
#pragma unroll
            for (int m = 0; m < 3; m++) {
                l[m] += vv[q] * swl[m * 128 + k];
                rr[m] += vv[q] * swr[m * 128 + k];
            }
        }
    }
    reinterpret_cast<float4*>(g_z)[r] = make_float4(l[0], l[1], l[2], 0.f);
#pragma unroll
    for (int m = 0; m < 3; m++) out[(size_t)r * 3 + m] = rr[m] + sb[m];
}

// ---------------- layer 3 part B: out += dinv * sum z[neighbors] ----------------
__global__ void k_gather3(float* __restrict__ out) {
    int n = blockIdx.x * blockDim.x + threadIdx.x;
    if (n >= NN) return;
    int beg = g_rowptr[n], end = g_rowptr[n + 1];
    const float4* z4 = reinterpret_cast<const float4*>(g_z);
    float4 acc = make_float4(0.f, 0.f, 0.f, 0.f);
    for (int i = beg; i < end; i++) {
        float4 v = z4[g_csr[i]];
        acc.x += v.x; acc.y += v.y; acc.z += v.z;
    }
    float di = g_dinv[n];
    out[(size_t)n * 3 + 0] += acc.x * di;
    out[(size_t)n * 3 + 1] += acc.y * di;
    out[(size_t)n * 3 + 2] += acc.z * di;
}

// ---------------- launch ----------------
extern "C" void kernel_launch(void* const* d_in, const int* in_sizes, int n_in,
                              void* d_out, int out_size) {
    (void)in_sizes; (void)n_in; (void)out_size;
    const float* x   = (const float*)d_in[0];
    const int*   ei  = (const int*)d_in[1];   // int32 view; k_edges auto-detects int64
    const float* W1l = (const float*)d_in[2];
    const float* b1  = (const float*)d_in[3];
    const float* W1r = (const float*)d_in[4];
    const float* W2l = (const float*)d_in[5];
    const float* b2  = (const float*)d_in[6];
    const float* W2r = (const float*)d_in[7];
    const float* W4l = (const float*)d_in[8];
    const float* b4  = (const float*)d_in[9];
    const float* W4r = (const float*)d_in[10];
    float* out = (float*)d_out;

    void *p_agg1, *p_agg2, *p_h1, *p_h2, *p_z;
    cudaGetSymbolAddress(&p_agg1, g_agg1);
    cudaGetSymbolAddress(&p_agg2, g_agg2);
    cudaGetSymbolAddress(&p_h1, g_h1);
    cudaGetSymbolAddress(&p_h2, g_h2);
    cudaGetSymbolAddress(&p_z, g_z);

    // smem sizes: (4 * 64 * (K/4+1)) float4 + 64 floats
    int smem40 = (4 * 64 * 11) * 16 + 256;   // 45312
    int smem64 = (4 * 64 * 17) * 16 + 256;   // 69888
    cudaFuncSetAttribute(k_layer<40, true>, cudaFuncAttributeMaxDynamicSharedMemorySize, smem40);
    cudaFuncSetAttribute(k_layer<64, true>, cudaFuncAttributeMaxDynamicSharedMemorySize, smem64);

    // CSR build
    k_zero0<<<(NN + 255) / 256, 256>>>();
    k_edges<<<(NE + 255) / 256, 256>>>(ei);
    k_scan1<<<SCAN_NB, SCAN_B>>>();
    k_scan2<<<1, 256>>>();
    k_scan3<<<(NN + 255) / 256, 256>>>();
    k_fill<<<(NE + 255) / 256, 256>>>();

    // layer 1: gather x (40 f = 10 f4), fused linear -> h1 [N,64]
    k_gather<10><<<(NN * 10 + 255) / 256, 256>>>(x, (float*)p_agg1);
    k_layer<40, true><<<dim3(296, 1), 256, smem40>>>(x, (const float*)p_agg1, W1l, b1, W1r,
                                                     (float*)p_h1, 64);

    // layer 2: gather h1 (64 f = 16 f4), fused linear -> h2 [N,128]
    k_gather<16><<<(NN * 16 + 255) / 256, 256>>>((const float*)p_h1, (float*)p_agg2);
    k_layer<64, true><<<dim3(296, 2), 256, smem64>>>((const float*)p_h1, (const float*)p_agg2,
                                                     W2l, b2, W2r, (float*)p_h2, 128);

    // layer 3: transform FIRST (3 outputs), aggregate only 4 floats/edge
    k_l3a<<<(NN + 127) / 128, 128>>>(W4l, b4, W4r, out);
    k_gather3<<<(NN + 255) / 256, 256>>>(out);
}

// round 4
// speedup vs baseline: 1.8737x; 1.8065x over previous
#include <cuda_runtime.h>
#include <cuda_bf16.h>
#include <cstdint>
#include <cstddef>

#define NN 100000
#define NE 1600000
#define SCAN_B 512
#define SCAN_NB ((NN + SCAN_B - 1) / SCAN_B)   // 196
#define NSM 152

// ---------------- scratch (static device globals; no allocs allowed) ----------------
__device__ int   g_degi[NN];
__device__ float g_dinv[NN];
__device__ int   g_src[NE];
__device__ int   g_dst[NE];
__device__ int   g_csr[NE];
__device__ int   g_rowptr[NN + 1];
__device__ int   g_cursor[NN];
__device__ int   g_bsum[256];
__device__ int   g_boff[256];
__device__ __align__(16) float g_agg1[(size_t)NN * 40];
__device__ __align__(16) float g_h1[(size_t)NN * 64];
__device__ __align__(16) float g_agg2[(size_t)NN * 64];
__device__ __align__(16) float g_h2[(size_t)NN * 128];
__device__ __align__(16) float g_z[(size_t)NN * 4];

// ==================== CSR build ====================
__global__ void k_zero0() {
    int i = blockIdx.x * blockDim.x + threadIdx.x;
    if (i < NN) g_degi[i] = 0;
}

__global__ void k_edges(const int* __restrict__ ei32) {
    bool is64 = true;
#pragma unroll
    for (int q = 1; q < 16; q += 2) is64 = is64 && (ei32[q] == 0);
    int e = blockIdx.x * blockDim.x + threadIdx.x;
    if (e >= NE) return;
    int s, d;
    if (is64) { s = ei32[2 * e];  d = ei32[2 * (NE + e)]; }
    else      { s = ei32[e];      d = ei32[NE + e]; }
    g_src[e] = s;
    g_dst[e] = d;
    atomicAdd(&g_degi[d], 1);
}

__global__ void k_scan1() {
    __shared__ int sh[SCAN_B];
    int i = blockIdx.x * SCAN_B + threadIdx.x;
    int v = (i < NN) ? g_degi[i] : 0;
    sh[threadIdx.x] = v;
    __syncthreads();
    for (int off = 1; off < SCAN_B; off <<= 1) {
        int t = (threadIdx.x >= off) ? sh[threadIdx.x - off] : 0;
        __syncthreads();
        sh[threadIdx.x] += t;
        __syncthreads();
    }
    if (i < NN) g_rowptr[i] = sh[threadIdx.x] - v;
    if (threadIdx.x == SCAN_B - 1) g_bsum[blockIdx.x] = sh[threadIdx.x];
}

__global__ void k_scan2() {
    __shared__ int sh[256];
    int t = threadIdx.x;
    int v = (t < SCAN_NB) ? g_bsum[t] : 0;
    sh[t] = v;
    __syncthreads();
    for (int off = 1; off < 256; off <<= 1) {
        int u = (t >= off) ? sh[t - off] : 0;
        __syncthreads();
        sh[t] += u;
        __syncthreads();
    }
    g_boff[t] = sh[t] - v;
}

__global__ void k_scan3() {
    int i = blockIdx.x * blockDim.x + threadIdx.x;
    if (i >= NN) return;
    int rp = g_rowptr[i] + g_boff[i / SCAN_B];
    g_rowptr[i] = rp;
    g_cursor[i] = rp;
    int d = g_degi[i];
    g_dinv[i] = (d > 0) ? (1.f / (float)d) : 0.f;
    if (i == 0) g_rowptr[NN] = NE;
}

__global__ void k_fill() {
    int e = blockIdx.x * blockDim.x + threadIdx.x;
    if (e >= NE) return;
    int pos = atomicAdd(&g_cursor[g_dst[e]], 1);
    g_csr[pos] = g_src[e];
}

// ==================== CSR gather: agg[n] = dinv[n]*sum feat[neighbors] ====================
template <int F4>
__global__ void k_gather(const float* __restrict__ feat, float* __restrict__ agg) {
    int t = blockIdx.x * blockDim.x + threadIdx.x;
    if (t >= NN * F4) return;
    int n = t / F4;
    int c = t - n * F4;
    int beg = g_rowptr[n], end = g_rowptr[n + 1];
    const float4* f = reinterpret_cast<const float4*>(feat);
    float4 acc = make_float4(0.f, 0.f, 0.f, 0.f);
    for (int i = beg; i < end; i++) {
        int s = g_csr[i];
        float4 v = f[(size_t)s * F4 + c];
        acc.x += v.x; acc.y += v.y; acc.z += v.z; acc.w += v.w;
    }
    float di = g_dinv[n];
    acc.x *= di; acc.y *= di; acc.z *= di; acc.w *= di;
    reinterpret_cast<float4*>(agg)[t] = acc;
}

// ==================== HMMA helpers ====================
__device__ __forceinline__ void mma_bf16(float* c, uint32_t a0, uint32_t a1,
                                         uint32_t a2, uint32_t a3,
                                         uint32_t b0, uint32_t b1) {
    asm volatile(
        "mma.sync.aligned.m16n8k16.row.col.f32.bf16.bf16.f32 "
        "{%0,%1,%2,%3}, {%4,%5,%6,%7}, {%8,%9}, {%0,%1,%2,%3};"
        : "+f"(c[0]), "+f"(c[1]), "+f"(c[2]), "+f"(c[3])
        : "r"(a0), "r"(a1), "r"(a2), "r"(a3), "r"(b0), "r"(b1));
}

__device__ __forceinline__ uint32_t pack_bf(float a, float b) {
    __nv_bfloat162 t = __floats2bfloat162_rn(a, b);
    return *reinterpret_cast<uint32_t*>(&t);
}

// split float4 -> hi/lo bf16x2 pairs, store 8B to each plane (addresses 8B-aligned)
__device__ __forceinline__ void store_hilo(char* pHi, char* pLo, float4 v) {
    float hx = __bfloat162float(__float2bfloat16_rn(v.x));
    float hy = __bfloat162float(__float2bfloat16_rn(v.y));
    float hz = __bfloat162float(__float2bfloat16_rn(v.z));
    float hw = __bfloat162float(__float2bfloat16_rn(v.w));
    *reinterpret_cast<uint2*>(pHi) = make_uint2(pack_bf(hx, hy), pack_bf(hz, hw));
    *reinterpret_cast<uint2*>(pLo) =
        make_uint2(pack_bf(v.x - hx, v.y - hy), pack_bf(v.z - hz, v.w - hw));
}

// ==================== fused SAGE layer via mma.sync (bf16 hi/lo split) ====================
// out[NN,NOUT] = act( [agg|in] @ [Wl;Wr]^T + b ); Kc = 2K, block tile 128 x NOUT.
// 8 warps: warp tile 32 rows x NOUT/2 cols.
template <int K, int NOUT, bool RELU>
__global__ void __launch_bounds__(256, 1) k_layer_mma(
        const float* __restrict__ in, const float* __restrict__ agg,
        const float* __restrict__ Wl, const float* __restrict__ bias,
        const float* __restrict__ Wr, float* __restrict__ out) {
    constexpr int Kc = 2 * K;
    constexpr int KSTEPS = Kc / 16;
    constexpr int K4 = Kc / 4;
    constexpr int SA = Kc + 8;           // bf16 elems per row (+16B pad: conflict-free frags)
    constexpr int SAB = SA * 2;          // row stride bytes
    constexpr int NT = (NOUT / 2) / 8;   // n8 tiles per warp
    constexpr int NTILES = (NN + 127) / 128;
    constexpr int OFF_AH = 512;
    constexpr int OFF_AL = OFF_AH + 128 * SAB;
    constexpr int OFF_BH = OFF_AL + 128 * SAB;
    constexpr int OFF_BL = OFF_BH + NOUT * SAB;

    extern __shared__ char smem[];
    float* sbias = reinterpret_cast<float*>(smem);
    char* sAh = smem + OFF_AH;
    char* sAl = smem + OFF_AL;
    char* sBh = smem + OFF_BH;
    char* sBl = smem + OFF_BL;

    int tid = threadIdx.x;
    int wid = tid >> 5, lane = tid & 31;
    int g = lane >> 2, tg = lane & 3;
    int mwarp = (wid & 3) * 32;
    int nwarp = (wid >> 2) * (NOUT / 2);

    if (tid < NOUT) sbias[tid] = bias[tid];
    // stage weights (concat along K), hi/lo split
    for (int idx = tid; idx < NOUT * K4; idx += 256) {
        int row = idx / K4, k4 = idx - row * K4;
        int k = k4 * 4;
        float4 v = (k < K)
            ? *reinterpret_cast<const float4*>(Wl + (size_t)row * K + k)
            : *reinterpret_cast<const float4*>(Wr + (size_t)row * K + (k - K));
        store_hilo(sBh + row * SAB + k * 2, sBl + row * SAB + k * 2, v);
    }
    __syncthreads();

    for (int tile = blockIdx.x; tile < NTILES; tile += gridDim.x) {
        int r0 = tile * 128;
        // stage A = [agg | in], hi/lo split
        for (int idx = tid; idx < 128 * K4; idx += 256) {
            int row = idx / K4, k4 = idx - row * K4;
            int k = k4 * 4;
            int gr = r0 + row;
            float4 v = make_float4(0.f, 0.f, 0.f, 0.f);
            if (gr < NN) {
                v = (k < K)
                    ? *reinterpret_cast<const float4*>(agg + (size_t)gr * K + k)
                    : *reinterpret_cast<const float4*>(in + (size_t)gr * K + (k - K));
            }
            store_hilo(sAh + row * SAB + k * 2, sAl + row * SAB + k * 2, v);
        }
        __syncthreads();

        float C[2][NT][4];
#pragma unroll
        for (int mt = 0; mt < 2; mt++)
#pragma unroll
            for (int nt = 0; nt < NT; nt++)
#pragma unroll
                for (int q = 0; q < 4; q++) C[mt][nt][q] = 0.f;

#pragma unroll
        for (int ks = 0; ks < KSTEPS; ks++) {
            int kb = ks * 16;
            uint32_t Ah[2][4], Al[2][4];
#pragma unroll
            for (int mt = 0; mt < 2; mt++) {
                const char* pa = sAh + (mwarp + mt * 16 + g) * SAB + kb * 2 + tg * 4;
                const char* pl = sAl + (mwarp + mt * 16 + g) * SAB + kb * 2 + tg * 4;
                Ah[mt][0] = *(const uint32_t*)(pa);
                Ah[mt][1] = *(const uint32_t*)(pa + 8 * SAB);
                Ah[mt][2] = *(const uint32_t*)(pa + 16);
                Ah[mt][3] = *(const uint32_t*)(pa + 8 * SAB + 16);
                Al[mt][0] = *(const uint32_t*)(pl);
                Al[mt][1] = *(const uint32_t*)(pl + 8 * SAB);
                Al[mt][2] = *(const uint32_t*)(pl + 16);
                Al[mt][3] = *(const uint32_t*)(pl + 8 * SAB + 16);
            }
            uint32_t Bh[NT][2], Bl[NT][2];
#pragma unroll
            for (int nt = 0; nt < NT; nt++) {
                const char* pb = sBh + (nwarp + nt * 8 + g) * SAB + kb * 2 + tg * 4;
                const char* pq = sBl + (nwarp + nt * 8 + g) * SAB + kb * 2 + tg * 4;
                Bh[nt][0] = *(const uint32_t*)(pb);
                Bh[nt][1] = *(const uint32_t*)(pb + 16);
                Bl[nt][0] = *(const uint32_t*)(pq);
                Bl[nt][1] = *(const uint32_t*)(pq + 16);
            }
#pragma unroll
            for (int mt = 0; mt < 2; mt++)
#pragma unroll
                for (int nt = 0; nt < NT; nt++) {
                    mma_bf16(C[mt][nt], Ah[mt][0], Ah[mt][1], Ah[mt][2], Ah[mt][3],
                             Bh[nt][0], Bh[nt][1]);
                    mma_bf16(C[mt][nt], Al[mt][0], Al[mt][1], Al[mt][2], Al[mt][3],
                             Bh[nt][0], Bh[nt][1]);
                    mma_bf16(C[mt][nt], Ah[mt][0], Ah[mt][1], Ah[mt][2], Ah[mt][3],
                             Bl[nt][0], Bl[nt][1]);
                }
        }
        __syncthreads();   // frags consumed; smem free for next tile's staging

        // epilogue: bias + relu, direct to gmem
#pragma unroll
        for (int mt = 0; mt < 2; mt++) {
            int rowA = r0 + mwarp + mt * 16 + g;
            int rowB = rowA + 8;
#pragma unroll
            for (int nt = 0; nt < NT; nt++) {
                int col = nwarp + nt * 8 + tg * 2;
                float bx = sbias[col], by = sbias[col + 1];
                if (rowA < NN) {
                    float2 o;
                    o.x = C[mt][nt][0] + bx;
                    o.y = C[mt][nt][1] + by;
                    if (RELU) { o.x = fmaxf(o.x, 0.f); o.y = fmaxf(o.y, 0.f); }
                    *reinterpret_cast<float2*>(&out[(size_t)rowA * NOUT + col]) = o;
                }
                if (rowB < NN) {
                    float2 o;
                    o.x = C[mt][nt][2] + bx;
                    o.y = C[mt][nt][3] + by;
                    if (RELU) { o.x = fmaxf(o.x, 0.f); o.y = fmaxf(o.y, 0.f); }
                    *reinterpret_cast<float2*>(&out[(size_t)rowB * NOUT + col]) = o;
                }
            }
        }
    }
}

// ==================== layer 3 ====================
__global__ void k_l3a(const float* __restrict__ W4l, const float* __restrict__ b4,
                      const float* __restrict__ W4r, float* __restrict__ out) {
    __shared__ float swl[384], swr[384], sb3[3];
    int tid = threadIdx.x;
    for (int i = tid; i < 384; i += blockDim.x) { swl[i] = W4l[i]; swr[i] = W4r[i]; }
    if (tid < 3) sb3[tid] = b4[tid];
    __syncthreads();
    int r = blockIdx.x * blockDim.x + tid;
    if (r >= NN) return;
    const float4* h = reinterpret_cast<const float4*>(g_h2 + (size_t)r * 128);
    float l[3] = {0.f, 0.f, 0.f};
    float rr[3] = {0.f, 0.f, 0.f};
#pragma unroll
    for (int k4 = 0; k4 < 32; k4++) {
        float4 v = h[k4];
        float vv[4] = {v.x, v.y, v.z, v.w};
#pragma unroll
        for (int q = 0; q < 4; q++) {
            int k = k4 * 4 + q;
#pragma unroll
            for (int m = 0; m < 3; m++) {
                l[m] += vv[q] * swl[m * 128 + k];
                rr[m] += vv[q] * swr[m * 128 + k];
            }
        }
    }
    reinterpret_cast<float4*>(g_z)[r] = make_float4(l[0], l[1], l[2], 0.f);
#pragma unroll
    for (int m = 0; m < 3; m++) out[(size_t)r * 3 + m] = rr[m] + sb3[m];
}

__global__ void k_gather3(float* __restrict__ out) {
    int n = blockIdx.x * blockDim.x + threadIdx.x;
    if (n >= NN) return;
    int beg = g_rowptr[n], end = g_rowptr[n + 1];
    const float4* z4 = reinterpret_cast<const float4*>(g_z);
    float4 acc = make_float4(0.f, 0.f, 0.f, 0.f);
    for (int i = beg; i < end; i++) {
        float4 v = z4[g_csr[i]];
        acc.x += v.x; acc.y += v.y; acc.z += v.z;
    }
    float di = g_dinv[n];
    out[(size_t)n * 3 + 0] += acc.x * di;
    out[(size_t)n * 3 + 1] += acc.y * di;
    out[(size_t)n * 3 + 2] += acc.z * di;
}

// ==================== launch ====================
extern "C" void kernel_launch(void* const* d_in, const int* in_sizes, int n_in,
                              void* d_out, int out_size) {
    (void)in_sizes; (void)n_in; (void)out_size;
    const float* x   = (const float*)d_in[0];
    const int*   ei  = (const int*)d_in[1];
    const float* W1l = (const float*)d_in[2];
    const float* b1  = (const float*)d_in[3];
    const float* W1r = (const float*)d_in[4];
    const float* W2l = (const float*)d_in[5];
    const float* b2  = (const float*)d_in[6];
    const float* W2r = (const float*)d_in[7];
    const float* W4l = (const float*)d_in[8];
    const float* b4  = (const float*)d_in[9];
    const float* W4r = (const float*)d_in[10];
    float* out = (float*)d_out;

    void *p_agg1, *p_agg2, *p_h1, *p_h2;
    cudaGetSymbolAddress(&p_agg1, g_agg1);
    cudaGetSymbolAddress(&p_agg2, g_agg2);
    cudaGetSymbolAddress(&p_h1, g_h1);
    cudaGetSymbolAddress(&p_h2, g_h2);

    // smem: 512 + 2*128*SAB + 2*NOUT*SAB
    int smem1 = 512 + 2 * 128 * (88 * 2) + 2 * 64 * (88 * 2);    // 68096
    int smem2 = 512 + 2 * 128 * (136 * 2) + 2 * 128 * (136 * 2); // 139776
    cudaFuncSetAttribute(k_layer_mma<40, 64, true>,
                         cudaFuncAttributeMaxDynamicSharedMemorySize, smem1);
    cudaFuncSetAttribute(k_layer_mma<64, 128, true>,
                         cudaFuncAttributeMaxDynamicSharedMemorySize, smem2);

    // CSR build
    k_zero0<<<(NN + 255) / 256, 256>>>();
    k_edges<<<(NE + 255) / 256, 256>>>(ei);
    k_scan1<<<SCAN_NB, SCAN_B>>>();
    k_scan2<<<1, 256>>>();
    k_scan3<<<(NN + 255) / 256, 256>>>();
    k_fill<<<(NE + 255) / 256, 256>>>();

    // layer 1
    k_gather<10><<<(NN * 10 + 255) / 256, 256>>>(x, (float*)p_agg1);
    k_layer_mma<40, 64, true><<<NSM, 256, smem1>>>(x, (const float*)p_agg1, W1l, b1, W1r,
                                                   (float*)p_h1);
    // layer 2
    k_gather<16><<<(NN * 16 + 255) / 256, 256>>>((const float*)p_h1, (float*)p_agg2);
    k_layer_mma<64, 128, true><<<NSM, 256, smem2>>>((const float*)p_h1, (const float*)p_agg2,
                                                    W2l, b2, W2r, (float*)p_h2);
    // layer 3
    k_l3a<<<(NN + 127) / 128, 128>>>(W4l, b4, W4r, out);
    k_gather3<<<(NN + 255) / 256, 256>>>(out);
}

// round 5
// speedup vs baseline: 2.0645x; 1.1018x over previous
#include <cuda_runtime.h>
#include <cuda_bf16.h>
#include <cstdint>
#include <cstddef>

#define NN 100000
#define NE 1600000
#define SCAN_B 512
#define SCAN_NB ((NN + SCAN_B - 1) / SCAN_B)   // 196
#define NSM 152

// ---------------- scratch (static device globals; no allocs allowed) ----------------
__device__ int   g_degi[NN];
__device__ float g_dinv[NN];
__device__ int   g_src[NE];
__device__ int   g_dst[NE];
__device__ int   g_csr[NE];
__device__ int   g_rowptr[NN + 1];
__device__ int   g_cursor[NN];
__device__ int   g_bsum[256];
__device__ __align__(16) float g_agg1[(size_t)NN * 40];
__device__ __align__(16) float g_h1[(size_t)NN * 64];
__device__ __align__(16) float g_agg2[(size_t)NN * 64];
__device__ __align__(16) float g_h2[(size_t)NN * 128];
__device__ __align__(16) float g_z[(size_t)NN * 4];

// ==================== CSR build ====================
__global__ void k_zero0() {
    int i = blockIdx.x * blockDim.x + threadIdx.x;
    if (i < NN) g_degi[i] = 0;
}

__global__ void k_edges(const int* __restrict__ ei32) {
    bool is64 = true;
#pragma unroll
    for (int q = 1; q < 16; q += 2) is64 = is64 && (ei32[q] == 0);
    int e = blockIdx.x * blockDim.x + threadIdx.x;
    if (e >= NE) return;
    int s, d;
    if (is64) { s = ei32[2 * e];  d = ei32[2 * (NE + e)]; }
    else      { s = ei32[e];      d = ei32[NE + e]; }
    g_src[e] = s;
    g_dst[e] = d;
    atomicAdd(&g_degi[d], 1);
}

// block-local inclusive scan + per-block sum + dinv
__global__ void k_scan1() {
    __shared__ int sh[SCAN_B];
    int i = blockIdx.x * SCAN_B + threadIdx.x;
    int v = (i < NN) ? g_degi[i] : 0;
    sh[threadIdx.x] = v;
    __syncthreads();
    for (int off = 1; off < SCAN_B; off <<= 1) {
        int t = (threadIdx.x >= off) ? sh[threadIdx.x - off] : 0;
        __syncthreads();
        sh[threadIdx.x] += t;
        __syncthreads();
    }
    if (i < NN) {
        g_rowptr[i] = sh[threadIdx.x] - v;  // block-local exclusive
        g_dinv[i] = (v > 0) ? (1.f / (float)v) : 0.f;
    }
    if (threadIdx.x == SCAN_B - 1) g_bsum[blockIdx.x] = sh[threadIdx.x];
}

// finalize rowptr/cursor; block offset = on-the-fly prefix over g_bsum (<=196, L1 broadcast)
__global__ void k_scanf() {
    int i = blockIdx.x * blockDim.x + threadIdx.x;
    if (i >= NN) return;
    int nb = i / SCAN_B;
    int off = 0;
    for (int b = 0; b < nb; b++) off += g_bsum[b];
    int rp = g_rowptr[i] + off;
    g_rowptr[i] = rp;
    g_cursor[i] = rp;
    if (i == 0) g_rowptr[NN] = NE;
}

__global__ void k_fill() {
    int e = blockIdx.x * blockDim.x + threadIdx.x;
    if (e >= NE) return;
    int pos = atomicAdd(&g_cursor[g_dst[e]], 1);
    g_csr[pos] = g_src[e];
}

// ==================== CSR gather: agg[n] = dinv[n]*sum feat[neighbors] ====================
// unroll x4, 4 independent accumulators -> MLP 4 per thread
template <int F4>
__global__ void k_gather(const float* __restrict__ feat, float* __restrict__ agg) {
    int t = blockIdx.x * blockDim.x + threadIdx.x;
    if (t >= NN * F4) return;
    int n = t / F4;
    int c = t - n * F4;
    int beg = g_rowptr[n], end = g_rowptr[n + 1];
    const float4* f = reinterpret_cast<const float4*>(feat);
    float4 a0 = make_float4(0.f, 0.f, 0.f, 0.f), a1 = a0, a2 = a0, a3 = a0;
    int i = beg;
    for (; i + 4 <= end; i += 4) {
        int s0 = g_csr[i], s1 = g_csr[i + 1], s2 = g_csr[i + 2], s3 = g_csr[i + 3];
        float4 v0 = f[(size_t)s0 * F4 + c];
        float4 v1 = f[(size_t)s1 * F4 + c];
        float4 v2 = f[(size_t)s2 * F4 + c];
        float4 v3 = f[(size_t)s3 * F4 + c];
        a0.x += v0.x; a0.y += v0.y; a0.z += v0.z; a0.w += v0.w;
        a1.x += v1.x; a1.y += v1.y; a1.z += v1.z; a1.w += v1.w;
        a2.x += v2.x; a2.y += v2.y; a2.z += v2.z; a2.w += v2.w;
        a3.x += v3.x; a3.y += v3.y; a3.z += v3.z; a3.w += v3.w;
    }
    for (; i < end; i++) {
        float4 v = f[(size_t)g_csr[i] * F4 + c];
        a0.x += v.x; a0.y += v.y; a0.z += v.z; a0.w += v.w;
    }
    float di = g_dinv[n];
    float4 acc;
    acc.x = ((a0.x + a1.x) + (a2.x + a3.x)) * di;
    acc.y = ((a0.y + a1.y) + (a2.y + a3.y)) * di;
    acc.z = ((a0.z + a1.z) + (a2.z + a3.z)) * di;
    acc.w = ((a0.w + a1.w) + (a2.w + a3.w)) * di;
    reinterpret_cast<float4*>(agg)[t] = acc;
}

// ==================== HMMA helpers ====================
__device__ __forceinline__ void mma_bf16(float* c, uint32_t a0, uint32_t a1,
                                         uint32_t a2, uint32_t a3,
                                         uint32_t b0, uint32_t b1) {
    asm volatile(
        "mma.sync.aligned.m16n8k16.row.col.f32.bf16.bf16.f32 "
        "{%0,%1,%2,%3}, {%4,%5,%6,%7}, {%8,%9}, {%0,%1,%2,%3};"
        : "+f"(c[0]), "+f"(c[1]), "+f"(c[2]), "+f"(c[3])
        : "r"(a0), "r"(a1), "r"(a2), "r"(a3), "r"(b0), "r"(b1));
}

__device__ __forceinline__ uint32_t pack_bf(float a, float b) {
    __nv_bfloat162 t = __floats2bfloat162_rn(a, b);
    return *reinterpret_cast<uint32_t*>(&t);
}

__device__ __forceinline__ void store_hilo(char* pHi, char* pLo, float4 v) {
    float hx = __bfloat162float(__float2bfloat16_rn(v.x));
    float hy = __bfloat162float(__float2bfloat16_rn(v.y));
    float hz = __bfloat162float(__float2bfloat16_rn(v.z));
    float hw = __bfloat162float(__float2bfloat16_rn(v.w));
    *reinterpret_cast<uint2*>(pHi) = make_uint2(pack_bf(hx, hy), pack_bf(hz, hw));
    *reinterpret_cast<uint2*>(pLo) =
        make_uint2(pack_bf(v.x - hx, v.y - hy), pack_bf(v.z - hz, v.w - hw));
}

// ==================== fused SAGE layer via mma.sync (bf16 hi/lo split) ====================
// Computes out[:, coloff : coloff+NOUTB] = act([agg|in] @ [Wl;Wr]^T + b) for a 64-col slab.
// Unified 64-col tile: layer1 = 1 slab (3 blocks/SM), layer2 = 2 slabs (2 blocks/SM).
template <int K, int NOUTB, bool RELU>
__global__ void __launch_bounds__(256) k_layer_mma(
        const float* __restrict__ in, const float* __restrict__ agg,
        const float* __restrict__ Wl, const float* __restrict__ bias,
        const float* __restrict__ Wr, float* __restrict__ out, int NOUT) {
    constexpr int Kc = 2 * K;
    constexpr int KSTEPS = Kc / 16;
    constexpr int K4 = Kc / 4;
    constexpr int SA = Kc + 8;           // +16B row pad: conflict-free frag loads
    constexpr int SAB = SA * 2;
    constexpr int NT = (NOUTB / 2) / 8;  // 4
    constexpr int NTILES = (NN + 127) / 128;
    constexpr int OFF_AH = 512;
    constexpr int OFF_AL = OFF_AH + 128 * SAB;
    constexpr int OFF_BH = OFF_AL + 128 * SAB;
    constexpr int OFF_BL = OFF_BH + NOUTB * SAB;

    extern __shared__ char smem[];
    float* sbias = reinterpret_cast<float*>(smem);
    char* sAh = smem + OFF_AH;
    char* sAl = smem + OFF_AL;
    char* sBh = smem + OFF_BH;
    char* sBl = smem + OFF_BL;

    int tid = threadIdx.x;
    int wid = tid >> 5, lane = tid & 31;
    int g = lane >> 2, tg = lane & 3;
    int mwarp = (wid & 3) * 32;
    int nwarp = (wid >> 2) * (NOUTB / 2);
    int coloff = blockIdx.y * NOUTB;

    if (tid < NOUTB) sbias[tid] = bias[coloff + tid];
    // stage this slab's weights (concat along K), hi/lo split
    for (int idx = tid; idx < NOUTB * K4; idx += 256) {
        int row = idx / K4, k4 = idx - row * K4;
        int k = k4 * 4;
        int grow = coloff + row;
        float4 v = (k < K)
            ? *reinterpret_cast<const float4*>(Wl + (size_t)grow * K + k)
            : *reinterpret_cast<const float4*>(Wr + (size_t)grow * K + (k - K));
        store_hilo(sBh + row * SAB + k * 2, sBl + row * SAB + k * 2, v);
    }
    __syncthreads();

    for (int tile = blockIdx.x; tile < NTILES; tile += gridDim.x) {
        int r0 = tile * 128;
        for (int idx = tid; idx < 128 * K4; idx += 256) {
            int row = idx / K4, k4 = idx - row * K4;
            int k = k4 * 4;
            int gr = r0 + row;
            float4 v = make_float4(0.f, 0.f, 0.f, 0.f);
            if (gr < NN) {
                v = (k < K)
                    ? *reinterpret_cast<const float4*>(agg + (size_t)gr * K + k)
                    : *reinterpret_cast<const float4*>(in + (size_t)gr * K + (k - K));
            }
            store_hilo(sAh + row * SAB + k * 2, sAl + row * SAB + k * 2, v);
        }
        __syncthreads();

        float C[2][NT][4];
#pragma unroll
        for (int mt = 0; mt < 2; mt++)
#pragma unroll
            for (int nt = 0; nt < NT; nt++)
#pragma unroll
                for (int q = 0; q < 4; q++) C[mt][nt][q] = 0.f;

#pragma unroll
        for (int ks = 0; ks < KSTEPS; ks++) {
            int kb = ks * 16;
            uint32_t Ah[2][4], Al[2][4];
#pragma unroll
            for (int mt = 0; mt < 2; mt++) {
                const char* pa = sAh + (mwarp + mt * 16 + g) * SAB + kb * 2 + tg * 4;
                const char* pl = sAl + (mwarp + mt * 16 + g) * SAB + kb * 2 + tg * 4;
                Ah[mt][0] = *(const uint32_t*)(pa);
                Ah[mt][1] = *(const uint32_t*)(pa + 8 * SAB);
                Ah[mt][2] = *(const uint32_t*)(pa + 16);
                Ah[mt][3] = *(const uint32_t*)(pa + 8 * SAB + 16);
                Al[mt][0] = *(const uint32_t*)(pl);
                Al[mt][1] = *(const uint32_t*)(pl + 8 * SAB);
                Al[mt][2] = *(const uint32_t*)(pl + 16);
                Al[mt][3] = *(const uint32_t*)(pl + 8 * SAB + 16);
            }
            uint32_t Bh[NT][2], Bl[NT][2];
#pragma unroll
            for (int nt = 0; nt < NT; nt++) {
                const char* pb = sBh + (nwarp + nt * 8 + g) * SAB + kb * 2 + tg * 4;
                const char* pq = sBl + (nwarp + nt * 8 + g) * SAB + kb * 2 + tg * 4;
                Bh[nt][0] = *(const uint32_t*)(pb);
                Bh[nt][1] = *(const uint32_t*)(pb + 16);
                Bl[nt][0] = *(const uint32_t*)(pq);
                Bl[nt][1] = *(const uint32_t*)(pq + 16);
            }
#pragma unroll
            for (int mt = 0; mt < 2; mt++)
#pragma unroll
                for (int nt = 0; nt < NT; nt++) {
                    mma_bf16(C[mt][nt], Ah[mt][0], Ah[mt][1], Ah[mt][2], Ah[mt][3],
                             Bh[nt][0], Bh[nt][1]);
                    mma_bf16(C[mt][nt], Al[mt][0], Al[mt][1], Al[mt][2], Al[mt][3],
                             Bh[nt][0], Bh[nt][1]);
                    mma_bf16(C[mt][nt], Ah[mt][0], Ah[mt][1], Ah[mt][2], Ah[mt][3],
                             Bl[nt][0], Bl[nt][1]);
                }
        }
        __syncthreads();

#pragma unroll
        for (int mt = 0; mt < 2; mt++) {
            int rowA = r0 + mwarp + mt * 16 + g;
            int rowB = rowA + 8;
#pragma unroll
            for (int nt = 0; nt < NT; nt++) {
                int lcol = nwarp + nt * 8 + tg * 2;
                int col = coloff + lcol;
                float bx = sbias[lcol], by = sbias[lcol + 1];
                if (rowA < NN) {
                    float2 o;
                    o.x = C[mt][nt][0] + bx;
                    o.y = C[mt][nt][1] + by;
                    if (RELU) { o.x = fmaxf(o.x, 0.f); o.y = fmaxf(o.y, 0.f); }
                    *reinterpret_cast<float2*>(&out[(size_t)rowA * NOUT + col]) = o;
                }
                if (rowB < NN) {
                    float2 o;
                    o.x = C[mt][nt][2] + bx;
                    o.y = C[mt][nt][3] + by;
                    if (RELU) { o.x = fmaxf(o.x, 0.f); o.y = fmaxf(o.y, 0.f); }
                    *reinterpret_cast<float2*>(&out[(size_t)rowB * NOUT + col]) = o;
                }
            }
        }
    }
}

// ==================== layer 3 ====================
__global__ void k_l3a(const float* __restrict__ W4l, const float* __restrict__ b4,
                      const float* __restrict__ W4r, float* __restrict__ out) {
    __shared__ float swl[384], swr[384], sb3[3];
    int tid = threadIdx.x;
    for (int i = tid; i < 384; i += blockDim.x) { swl[i] = W4l[i]; swr[i] = W4r[i]; }
    if (tid < 3) sb3[tid] = b4[tid];
    __syncthreads();
    int r = blockIdx.x * blockDim.x + tid;
    if (r >= NN) return;
    const float4* h = reinterpret_cast<const float4*>(g_h2 + (size_t)r * 128);
    float l[3] = {0.f, 0.f, 0.f};
    float rr[3] = {0.f, 0.f, 0.f};
#pragma unroll
    for (int k4 = 0; k4 < 32; k4++) {
        float4 v = h[k4];
        float vv[4] = {v.x, v.y, v.z, v.w};
#pragma unroll
        for (int q = 0; q < 4; q++) {
            int k = k4 * 4 + q;
#pragma unroll
            for (int m = 0; m < 3; m++) {
                l[m] += vv[q] * swl[m * 128 + k];
                rr[m] += vv[q] * swr[m * 128 + k];
            }
        }
    }
    reinterpret_cast<float4*>(g_z)[r] = make_float4(l[0], l[1], l[2], 0.f);
#pragma unroll
    for (int m = 0; m < 3; m++) out[(size_t)r * 3 + m] = rr[m] + sb3[m];
}

__global__ void k_gather3(float* __restrict__ out) {
    int n = blockIdx.x * blockDim.x + threadIdx.x;
    if (n >= NN) return;
    int beg = g_rowptr[n], end = g_rowptr[n + 1];
    const float4* z4 = reinterpret_cast<const float4*>(g_z);
    float4 a0 = make_float4(0.f, 0.f, 0.f, 0.f), a1 = a0;
    int i = beg;
    for (; i + 2 <= end; i += 2) {
        float4 v0 = z4[g_csr[i]];
        float4 v1 = z4[g_csr[i + 1]];
        a0.x += v0.x; a0.y += v0.y; a0.z += v0.z;
        a1.x += v1.x; a1.y += v1.y; a1.z += v1.z;
    }
    if (i < end) {
        float4 v = z4[g_csr[i]];
        a0.x += v.x; a0.y += v.y; a0.z += v.z;
    }
    float di = g_dinv[n];
    out[(size_t)n * 3 + 0] += (a0.x + a1.x) * di;
    out[(size_t)n * 3 + 1] += (a0.y + a1.y) * di;
    out[(size_t)n * 3 + 2] += (a0.z + a1.z) * di;
}

// ==================== launch ====================
extern "C" void kernel_launch(void* const* d_in, const int* in_sizes, int n_in,
                              void* d_out, int out_size) {
    (void)in_sizes; (void)n_in; (void)out_size;
    const float* x   = (const float*)d_in[0];
    const int*   ei  = (const int*)d_in[1];
    const float* W1l = (const float*)d_in[2];
    const float* b1  = (const float*)d_in[3];
    const float* W1r = (const float*)d_in[4];
    const float* W2l = (const float*)d_in[5];
    const float* b2  = (const float*)d_in[6];
    const float* W2r = (const float*)d_in[7];
    const float* W4l = (const float*)d_in[8];
    const float* b4  = (const float*)d_in[9];
    const float* W4r = (const float*)d_in[10];
    float* out = (float*)d_out;

    void *p_agg1, *p_agg2, *p_h1, *p_h2;
    cudaGetSymbolAddress(&p_agg1, g_agg1);
    cudaGetSymbolAddress(&p_agg2, g_agg2);
    cudaGetSymbolAddress(&p_h1, g_h1);
    cudaGetSymbolAddress(&p_h2, g_h2);

    // smem: 512 + 2*128*SAB + 2*64*SAB
    int smem1 = 512 + 2 * 128 * (88 * 2) + 2 * 64 * (88 * 2);     // 68096  -> 3 blocks/SM
    int smem2 = 512 + 2 * 128 * (136 * 2) + 2 * 64 * (136 * 2);   // 104960 -> 2 blocks/SM
    cudaFuncSetAttribute(k_layer_mma<40, 64, true>,
                         cudaFuncAttributeMaxDynamicSharedMemorySize, smem1);
    cudaFuncSetAttribute(k_layer_mma<64, 64, true>,
                         cudaFuncAttributeMaxDynamicSharedMemorySize, smem2);

    // CSR build
    k_zero0<<<(NN + 255) / 256, 256>>>();
    k_edges<<<(NE + 255) / 256, 256>>>(ei);
    k_scan1<<<SCAN_NB, SCAN_B>>>();
    k_scanf<<<(NN + 255) / 256, 256>>>();
    k_fill<<<(NE + 255) / 256, 256>>>();

    // layer 1: gather x, fused linear -> h1 [N,64] (one 64-col slab, 3 blocks/SM)
    k_gather<10><<<(NN * 10 + 255) / 256, 256>>>(x, (float*)p_agg1);
    k_layer_mma<40, 64, true><<<dim3(3 * NSM, 1), 256, smem1>>>(
        x, (const float*)p_agg1, W1l, b1, W1r, (float*)p_h1, 64);

    // layer 2: gather h1, fused linear -> h2 [N,128] (two 64-col slabs, 2 blocks/SM)
    k_gather<16><<<(NN * 16 + 255) / 256, 256>>>((const float*)p_h1, (float*)p_agg2);
    k_layer_mma<64, 64, true><<<dim3(NSM, 2), 256, smem2>>>(
        (const float*)p_h1, (const float*)p_agg2, W2l, b2, W2r, (float*)p_h2, 128);

    // layer 3: transform FIRST (3 outputs), aggregate 4 floats/edge
    k_l3a<<<(NN + 127) / 128, 128>>>(W4l, b4, W4r, out);
    k_gather3<<<(NN + 255) / 256, 256>>>(out);
}